// round 3
// baseline (speedup 1.0000x reference)
#include <cuda_runtime.h>
#include <cstdint>

// ---------------------------------------------------------------------------
// Problem: z = z_roi @ w_emb + b   [2048 x 65536] @ [65536 x 256]
//          z_all = mask ? z : 0
//          s = mask ? student_t(z, centroids) : 0   (alpha = 1 -> 1/(1+dist))
//          c = argmax_k s
// Output layout: [z_all (M*NDF) | s (M*K) | c (M)] all float32.
// mask arrives as int32 (bool promoted by the harness).
// ---------------------------------------------------------------------------

#define TM 32
#define TN 128
#define TK 32

__global__ __launch_bounds__(256) void emb_gemm_kernel(
    const float* __restrict__ A,            // [M, Kdim]
    const float* __restrict__ B,            // [Kdim, N]
    const float* __restrict__ bias,         // [N]
    const int* __restrict__ mask,           // [M] (int32 bool)
    float* __restrict__ C,                  // [M, N]
    int M, int Kdim, int N)
{
    __shared__ float As[TK][TM + 1];                 // transposed, +1 pad
    __shared__ __align__(16) float Bs[TK][TN];

    const int tid = threadIdx.x;
    const int block_m = blockIdx.x * TM;
    const int block_n = blockIdx.y * TN;

    const int tx = tid & 31;   // 0..31 -> 4-col group
    const int ty = tid >> 5;   // 0..7  -> 4-row group

    // A tile load map: one float4 per thread (32x32 tile = 256 float4)
    const int a_row = tid >> 3;          // 0..31
    const int a_col = (tid & 7) << 2;    // 0,4,...,28
    // B tile load map: four float4 per thread (32x128 tile)
    const int b_col  = (tid & 31) << 2;  // 0..124
    const int b_row0 = tid >> 5;         // 0..7

    const float* Ap = A + (size_t)(block_m + a_row) * Kdim + a_col;
    const float* Bp = B + block_n + b_col;

    float acc[4][4];
    #pragma unroll
    for (int i = 0; i < 4; i++)
        #pragma unroll
        for (int j = 0; j < 4; j++)
            acc[i][j] = 0.0f;

    // prefetch first tiles into registers
    float4 a_reg = *reinterpret_cast<const float4*>(Ap);
    float4 b_reg[4];
    #pragma unroll
    for (int i = 0; i < 4; i++)
        b_reg[i] = *reinterpret_cast<const float4*>(Bp + (size_t)(b_row0 + 8 * i) * N);

    for (int k0 = 0; k0 < Kdim; k0 += TK) {
        // registers -> shared
        As[a_col + 0][a_row] = a_reg.x;
        As[a_col + 1][a_row] = a_reg.y;
        As[a_col + 2][a_row] = a_reg.z;
        As[a_col + 3][a_row] = a_reg.w;
        #pragma unroll
        for (int i = 0; i < 4; i++)
            *reinterpret_cast<float4*>(&Bs[b_row0 + 8 * i][b_col]) = b_reg[i];
        __syncthreads();

        // prefetch next tiles (latency hidden by the compute below)
        if (k0 + TK < Kdim) {
            a_reg = *reinterpret_cast<const float4*>(Ap + k0 + TK);
            #pragma unroll
            for (int i = 0; i < 4; i++)
                b_reg[i] = *reinterpret_cast<const float4*>(
                    Bp + (size_t)(k0 + TK + b_row0 + 8 * i) * N);
        }

        #pragma unroll
        for (int k = 0; k < TK; k++) {
            float a0 = As[k][(ty << 2) + 0];
            float a1 = As[k][(ty << 2) + 1];
            float a2 = As[k][(ty << 2) + 2];
            float a3 = As[k][(ty << 2) + 3];
            float4 bv = *reinterpret_cast<const float4*>(&Bs[k][tx << 2]);
            acc[0][0] += a0 * bv.x; acc[0][1] += a0 * bv.y;
            acc[0][2] += a0 * bv.z; acc[0][3] += a0 * bv.w;
            acc[1][0] += a1 * bv.x; acc[1][1] += a1 * bv.y;
            acc[1][2] += a1 * bv.z; acc[1][3] += a1 * bv.w;
            acc[2][0] += a2 * bv.x; acc[2][1] += a2 * bv.y;
            acc[2][2] += a2 * bv.z; acc[2][3] += a2 * bv.w;
            acc[3][0] += a3 * bv.x; acc[3][1] += a3 * bv.y;
            acc[3][2] += a3 * bv.z; acc[3][3] += a3 * bv.w;
        }
        __syncthreads();
    }

    // epilogue: bias + mask, vectorized store
    #pragma unroll
    for (int i = 0; i < 4; i++) {
        const int row = block_m + (ty << 2) + i;
        const float mval = mask[row] ? 1.0f : 0.0f;
        const int col = block_n + (tx << 2);
        float4 ov;
        ov.x = (acc[i][0] + bias[col + 0]) * mval;
        ov.y = (acc[i][1] + bias[col + 1]) * mval;
        ov.z = (acc[i][2] + bias[col + 2]) * mval;
        ov.w = (acc[i][3] + bias[col + 3]) * mval;
        *reinterpret_cast<float4*>(&C[(size_t)row * N + col]) = ov;
    }
}

// ---------------------------------------------------------------------------
// Per-row student-t + normalize + argmax. One block per (b, s) row.
// K <= 128, NDF multiple of 4.
// ---------------------------------------------------------------------------
__global__ __launch_bounds__(128) void cluster_kernel(
    const float* __restrict__ Z,            // [M, NDF] (already masked)
    const float* __restrict__ cent,         // [K, NDF]
    const int* __restrict__ mask,           // [M] (int32 bool)
    float* __restrict__ S,                  // [M, K]
    float* __restrict__ Cidx,               // [M]
    int NDF, int K)
{
    const int row = blockIdx.x;
    const int tid = threadIdx.x;

    __shared__ __align__(16) float zs[256];
    __shared__ float stmp[128];
    __shared__ float red_sum;
    __shared__ int   red_idx;

    for (int i = tid; i < NDF; i += blockDim.x)
        zs[i] = Z[(size_t)row * NDF + i];
    __syncthreads();

    float val = 0.0f;
    if (tid < K) {
        const float4* c4 = reinterpret_cast<const float4*>(cent + (size_t)tid * NDF);
        const float4* z4 = reinterpret_cast<const float4*>(zs);
        float d2 = 0.0f;
        #pragma unroll 8
        for (int j = 0; j < NDF / 4; j++) {
            float4 cv = c4[j];
            float4 zv = z4[j];
            float dx = zv.x - cv.x;
            float dy = zv.y - cv.y;
            float dz = zv.z - cv.z;
            float dw = zv.w - cv.w;
            d2 += dx * dx + dy * dy + dz * dz + dw * dw;
        }
        float dist = sqrtf(fmaxf(d2, 0.0f));
        // alpha = 1: (1 + dist)^(-(1+1)/2) = 1/(1+dist)
        val = 1.0f / (1.0f + dist);
    }
    stmp[tid] = val;
    __syncthreads();

    // warp 0 reduces sum and argmax (first max index, matching jnp.argmax)
    if (tid < 32) {
        float sum = 0.0f;
        float best = -1.0f;
        int bidx = 0;
        for (int k = tid; k < K; k += 32) {
            float v = stmp[k];
            sum += v;
            if (v > best) { best = v; bidx = k; }
        }
        #pragma unroll
        for (int off = 16; off > 0; off >>= 1) {
            sum += __shfl_down_sync(0xffffffffu, sum, off);
            float ob = __shfl_down_sync(0xffffffffu, best, off);
            int   oi = __shfl_down_sync(0xffffffffu, bidx, off);
            if (ob > best || (ob == best && oi < bidx)) { best = ob; bidx = oi; }
        }
        if (tid == 0) { red_sum = sum; red_idx = bidx; }
    }
    __syncthreads();

    const bool mrow = mask[row] != 0;
    const float inv = mrow ? (1.0f / red_sum) : 0.0f;
    if (tid < K)
        S[(size_t)row * K + tid] = val * inv;
    if (tid == 0)
        Cidx[row] = mrow ? (float)red_idx : 0.0f;
}

// ---------------------------------------------------------------------------
extern "C" void kernel_launch(void* const* d_in, const int* in_sizes, int n_in,
                              void* d_out, int out_size)
{
    const float* z_roi = (const float*)d_in[0];   // [M, Kdim]
    const int*   mask  = (const int*)d_in[1];     // [M] bool -> int32
    const float* w_emb = (const float*)d_in[2];   // [Kdim, NDF]
    const float* b_emb = (const float*)d_in[3];   // [NDF]
    const float* cent  = (const float*)d_in[4];   // [K, NDF]

    const int M    = in_sizes[1];            // 2048 (= BN*SN)
    const int Kdim = in_sizes[0] / M;        // 65536
    const int NDF  = in_sizes[3];            // 256
    const int NC   = in_sizes[4] / NDF;      // 100

    float* out  = (float*)d_out;
    float* zall = out;                                   // [M, NDF]
    float* S    = out + (size_t)M * NDF;                 // [M, NC]
    float* Cx   = S + (size_t)M * NC;                    // [M]

    dim3 grid(M / TM, NDF / TN);
    emb_gemm_kernel<<<grid, 256>>>(z_roi, w_emb, b_emb, mask, zall, M, Kdim, NDF);
    cluster_kernel<<<M, 128>>>(zall, cent, mask, S, Cx, NDF, NC);
}

// round 5
// speedup vs baseline: 2.5951x; 2.5951x over previous
#include <cuda_runtime.h>
#include <cuda_bf16.h>
#include <cstdint>

#define KDIM   65536
#define MROWS  2048
#define NDFv   256
#define NCv    100
#define SPLITS 4
#define KPS    (KDIM / SPLITS)   // 16384
#define KC     64
#define NCHUNK (KPS / KC)        // 256
#define STAGE  65536
#define OFF_AHI 0
#define OFF_ALO 16384
#define OFF_BHI 32768
#define OFF_BLO 49152
#define SMEM_TOTAL (2 * STAGE)   // 128 KB

// device-global scratch (no cudaMalloc allowed)
__device__ __align__(16) unsigned short g_Bt_hi[(size_t)NDFv * KDIM]; // [n][k] bf16
__device__ __align__(16) unsigned short g_Bt_lo[(size_t)NDFv * KDIM];
__device__ float g_partial[(size_t)SPLITS * MROWS * NDFv];            // [split][row][col]

// ---------------- helpers (sm_80-class PTX only: valid on compute_103) ------
__device__ __forceinline__ uint32_t smem_u32(const void* p) {
    uint32_t a;
    asm("{ .reg .u64 t; cvta.to.shared.u64 t, %1; cvt.u32.u64 %0, t; }" : "=r"(a) : "l"(p));
    return a;
}
__device__ __forceinline__ uint32_t pack2(float lo, float hi) { // low half = bf16(lo)
    uint32_t r;
    asm("cvt.rn.bf16x2.f32 %0, %1, %2;" : "=r"(r) : "f"(hi), "f"(lo));
    return r;
}
#define STS64V(a, r0, r1) \
    asm volatile("st.shared.v2.b32 [%0], {%1,%2};" :: "r"(a), "r"(r0), "r"(r1) : "memory")
#define CP_ASYNC16(dst, src) \
    asm volatile("cp.async.cg.shared.global [%0], [%1], 16;" :: "r"(dst), "l"(src) : "memory")
#define CP_COMMIT() asm volatile("cp.async.commit_group;" ::: "memory")
#define CP_WAIT0()  asm volatile("cp.async.wait_group 0;" ::: "memory")

__device__ __forceinline__ void ldsm4(uint32_t r[4], uint32_t a) {
    asm volatile("ldmatrix.sync.aligned.m8n8.x4.shared.b16 {%0,%1,%2,%3}, [%4];"
                 : "=r"(r[0]), "=r"(r[1]), "=r"(r[2]), "=r"(r[3]) : "r"(a));
}
__device__ __forceinline__ void mma16816(float d[4], const uint32_t a[4],
                                         uint32_t b0, uint32_t b1) {
    asm volatile("mma.sync.aligned.m16n8k16.row.col.f32.bf16.bf16.f32 "
                 "{%0,%1,%2,%3},{%4,%5,%6,%7},{%8,%9},{%0,%1,%2,%3};"
                 : "+f"(d[0]), "+f"(d[1]), "+f"(d[2]), "+f"(d[3])
                 : "r"(a[0]), "r"(a[1]), "r"(a[2]), "r"(a[3]), "r"(b0), "r"(b1));
}

// ---------------- prepass: w_emb [K,256] fp32 -> g_Bt_{hi,lo} [256][K] bf16 --
__global__ __launch_bounds__(256) void split_transpose_kernel(const float* __restrict__ W) {
    __shared__ float tile[32][33];
    const int k0 = blockIdx.x * 32, n0 = blockIdx.y * 32;
    const int tx = threadIdx.x & 31, ty = threadIdx.x >> 5;
    #pragma unroll
    for (int i = 0; i < 4; i++)
        tile[ty * 4 + i][tx] = W[(size_t)(k0 + ty * 4 + i) * NDFv + n0 + tx];
    __syncthreads();
    #pragma unroll
    for (int i = 0; i < 4; i++) {
        const int n = ty * 4 + i;
        const float v = tile[tx][n];
        __nv_bfloat16 h = __float2bfloat16(v);
        __nv_bfloat16 l = __float2bfloat16(v - __bfloat162float(h));
        const size_t idx = (size_t)(n0 + n) * KDIM + k0 + tx;
        g_Bt_hi[idx] = *(unsigned short*)&h;
        g_Bt_lo[idx] = *(unsigned short*)&l;
    }
}

// ---------------- GEMM: mma.sync bf16 3-way split, split-K partials ---------
__global__ __launch_bounds__(256, 1) void gemm_mma_kernel(const float* __restrict__ A) {
    extern __shared__ char smem_dyn[];
    const uint32_t sbase = smem_u32(smem_dyn);
    const int tid = threadIdx.x;
    const int wid = tid >> 5, lane = tid & 31;
    const int mtile = blockIdx.x & 15;
    const int ntile = (blockIdx.x >> 4) & 1;
    const int split = blockIdx.x >> 5;
    const int wm = wid & 1, wn = wid >> 1;   // warp tile: m64 x n32

    // loader mapping: 2 threads per row, each handles 32 k (64B)
    const int arow = tid >> 1, ahalf = tid & 1;
    const uint32_t xsts = (uint32_t)((arow & 7) << 4);
    const float* Ag = A + (size_t)(mtile * 128 + arow) * KDIM + (size_t)split * KPS + ahalf * 32;
    const unsigned short* Bhg = g_Bt_hi + (size_t)(ntile * 128 + arow) * KDIM + (size_t)split * KPS + ahalf * 32;
    const unsigned short* Blg = g_Bt_lo + (size_t)(ntile * 128 + arow) * KDIM + (size_t)split * KPS + ahalf * 32;

    // ldmatrix lane mapping (shared by A and B frags)
    const int a_r  = (lane & 7) + ((lane >> 3) & 1) * 8;        // row within 16
    const uint32_t a_c16 = (uint32_t)(((lane >> 4) & 1) * 16);  // 16B column select
    const uint32_t xf = (uint32_t)((a_r & 7) << 4);
    uint32_t colx[4];
    #pragma unroll
    for (int ks = 0; ks < 4; ks++) colx[ks] = (((uint32_t)ks << 5) | a_c16) ^ xf;

    float acc[4][4][4] = {};
    float4 a_ld[8];

    // prologue: A regs + B cp.async for chunk 0 into stage 0
    #pragma unroll
    for (int i = 0; i < 8; i++) a_ld[i] = *(const float4*)(Ag + i * 4);
    #pragma unroll
    for (int j = 0; j < 4; j++) {
        const uint32_t off = (uint32_t)(arow * 128) + ((((uint32_t)(ahalf * 4 + j)) << 4) ^ xsts);
        CP_ASYNC16(sbase + OFF_BHI + off, Bhg + j * 8);
        CP_ASYNC16(sbase + OFF_BLO + off, Blg + j * 8);
    }
    CP_COMMIT();

    for (int it = 0; it < NCHUNK; it++) {
        const uint32_t st = sbase + (uint32_t)((it & 1) * STAGE);

        // A: fp32 regs -> bf16 hi/lo -> swizzled STS
        #pragma unroll
        for (int i = 0; i < 8; i++) {
            const float4 f = a_ld[i];
            const uint32_t h0 = pack2(f.x, f.y);
            const uint32_t h1 = pack2(f.z, f.w);
            const uint32_t l0 = pack2(f.x - __uint_as_float(h0 << 16),
                                      f.y - __uint_as_float(h0 & 0xffff0000u));
            const uint32_t l1 = pack2(f.z - __uint_as_float(h1 << 16),
                                      f.w - __uint_as_float(h1 & 0xffff0000u));
            const uint32_t off = (uint32_t)(arow * 128) +
                                 ((((uint32_t)(ahalf * 64 + i * 8))) ^ xsts);
            STS64V(st + OFF_AHI + off, h0, h1);
            STS64V(st + OFF_ALO + off, l0, l1);
        }
        CP_WAIT0();
        __syncthreads();

        // prefetch next chunk (A regs via LDG, B via cp.async into other stage)
        if (it + 1 < NCHUNK) {
            const float* Ap = Ag + (size_t)(it + 1) * KC;
            #pragma unroll
            for (int i = 0; i < 8; i++) a_ld[i] = *(const float4*)(Ap + i * 4);
            const uint32_t st2 = sbase + (uint32_t)(((it + 1) & 1) * STAGE);
            const unsigned short* Bhp = Bhg + (size_t)(it + 1) * KC;
            const unsigned short* Blp = Blg + (size_t)(it + 1) * KC;
            #pragma unroll
            for (int j = 0; j < 4; j++) {
                const uint32_t off = (uint32_t)(arow * 128) +
                                     ((((uint32_t)(ahalf * 4 + j)) << 4) ^ xsts);
                CP_ASYNC16(st2 + OFF_BHI + off, Bhp + j * 8);
                CP_ASYNC16(st2 + OFF_BLO + off, Blp + j * 8);
            }
            CP_COMMIT();
        }

        // tensor-core mainloop over stage st
        #pragma unroll
        for (int ks = 0; ks < 4; ks++) {
            uint32_t ah[4][4], al[4][4];
            #pragma unroll
            for (int mf = 0; mf < 4; mf++) {
                const uint32_t ro = (uint32_t)((wm * 64 + mf * 16 + a_r) * 128) + colx[ks];
                ldsm4(ah[mf], st + OFF_AHI + ro);
                ldsm4(al[mf], st + OFF_ALO + ro);
            }
            uint32_t bh[2][4], bl[2][4];
            #pragma unroll
            for (int g = 0; g < 2; g++) {
                const uint32_t ro = (uint32_t)((wn * 32 + g * 16 + a_r) * 128) + colx[ks];
                ldsm4(bh[g], st + OFF_BHI + ro);
                ldsm4(bl[g], st + OFF_BLO + ro);
            }
            #pragma unroll
            for (int mf = 0; mf < 4; mf++)
                #pragma unroll
                for (int nf = 0; nf < 4; nf++) {
                    const uint32_t b0 = bh[nf >> 1][nf & 1];
                    const uint32_t b1 = bh[nf >> 1][(nf & 1) + 2];
                    const uint32_t c0 = bl[nf >> 1][nf & 1];
                    const uint32_t c1 = bl[nf >> 1][(nf & 1) + 2];
                    mma16816(acc[mf][nf], ah[mf], b0, b1);  // Ahi*Bhi
                    mma16816(acc[mf][nf], al[mf], b0, b1);  // Alo*Bhi
                    mma16816(acc[mf][nf], ah[mf], c0, c1);  // Ahi*Blo
                }
        }
    }

    // epilogue: write split partials [split][row][col]
    float* pbase = g_partial + (size_t)split * MROWS * NDFv;
    #pragma unroll
    for (int mf = 0; mf < 4; mf++)
        #pragma unroll
        for (int nf = 0; nf < 4; nf++) {
            const int row = mtile * 128 + wm * 64 + mf * 16 + (lane >> 2);
            const int col = ntile * 128 + wn * 32 + nf * 8 + (lane & 3) * 2;
            float* p = pbase + (size_t)row * NDFv + col;
            *(float2*)p = make_float2(acc[mf][nf][0], acc[mf][nf][1]);
            *(float2*)(p + 8 * NDFv) = make_float2(acc[mf][nf][2], acc[mf][nf][3]);
        }
}

// ---------------- split-K reduce: zall = (sum partials + bias) * mask -------
__global__ __launch_bounds__(256) void reduce_kernel(const float* __restrict__ bias,
                                                     const int* __restrict__ mask,
                                                     float* __restrict__ zall) {
    const int i = blockIdx.x * 256 + threadIdx.x;   // 0 .. 262143 (float2 units)
    const int row = i >> 7;
    const int col = (i & 127) * 2;
    float2 s = make_float2(0.f, 0.f);
    #pragma unroll
    for (int sp = 0; sp < SPLITS; sp++) {
        const float2 v = *(const float2*)&g_partial[(size_t)sp * MROWS * NDFv +
                                                    (size_t)row * NDFv + col];
        s.x += v.x; s.y += v.y;
    }
    const float m = mask[row] ? 1.0f : 0.0f;
    s.x = (s.x + bias[col]) * m;
    s.y = (s.y + bias[col + 1]) * m;
    *(float2*)&zall[(size_t)row * NDFv + col] = s;
}

// ---------------- student-t + normalize + argmax (8 rows / block) -----------
__global__ __launch_bounds__(128) void cluster_kernel(const float* __restrict__ Z,
                                                      const float* __restrict__ cent,
                                                      const int* __restrict__ mask,
                                                      float* __restrict__ S,
                                                      float* __restrict__ Cidx) {
    const int tid = threadIdx.x;
    const int row0 = blockIdx.x * 8;
    __shared__ __align__(16) float zs[8][256];
    __shared__ float stmp[128];
    __shared__ float red_s;
    __shared__ int   red_i;

    #pragma unroll
    for (int i = 0; i < 16; i++) {
        const int idx = i * 128 + tid;
        zs[idx >> 8][idx & 255] = Z[(size_t)row0 * 256 + idx];
    }
    __syncthreads();

    for (int r = 0; r < 8; r++) {
        float val = 0.0f;
        if (tid < NCv) {
            const float4* c4 = (const float4*)(cent + (size_t)tid * NDFv);
            const float4* z4 = (const float4*)zs[r];
            float d2 = 0.0f;
            #pragma unroll 8
            for (int j = 0; j < NDFv / 4; j++) {
                const float4 cv = c4[j];
                const float4 zv = z4[j];
                const float dx = zv.x - cv.x, dy = zv.y - cv.y;
                const float dz = zv.z - cv.z, dw = zv.w - cv.w;
                d2 += dx * dx + dy * dy + dz * dz + dw * dw;
            }
            val = 1.0f / (1.0f + sqrtf(fmaxf(d2, 0.0f)));
        }
        stmp[tid] = val;
        __syncthreads();
        if (tid < 32) {
            float sum = 0.0f, best = -1.0f;
            int bidx = 0;
            for (int k = tid; k < NCv; k += 32) {
                const float v = stmp[k];
                sum += v;
                if (v > best) { best = v; bidx = k; }
            }
            #pragma unroll
            for (int off = 16; off > 0; off >>= 1) {
                sum += __shfl_down_sync(0xffffffffu, sum, off);
                const float ob = __shfl_down_sync(0xffffffffu, best, off);
                const int   oi = __shfl_down_sync(0xffffffffu, bidx, off);
                if (ob > best || (ob == best && oi < bidx)) { best = ob; bidx = oi; }
            }
            if (tid == 0) { red_s = sum; red_i = bidx; }
        }
        __syncthreads();
        const int row = row0 + r;
        const bool m = mask[row] != 0;
        const float inv = m ? (1.0f / red_s) : 0.0f;
        if (tid < NCv) S[(size_t)row * NCv + tid] = val * inv;
        if (tid == 0)  Cidx[row] = m ? (float)red_i : 0.0f;
        __syncthreads();
    }
}

// ---------------------------------------------------------------------------
extern "C" void kernel_launch(void* const* d_in, const int* in_sizes, int n_in,
                              void* d_out, int out_size) {
    (void)in_sizes; (void)n_in; (void)out_size;
    const float* z_roi = (const float*)d_in[0];
    const int*   mask  = (const int*)d_in[1];
    const float* w_emb = (const float*)d_in[2];
    const float* b_emb = (const float*)d_in[3];
    const float* cent  = (const float*)d_in[4];

    float* out  = (float*)d_out;
    float* zall = out;
    float* S    = out + (size_t)MROWS * NDFv;
    float* Cx   = S + (size_t)MROWS * NCv;

    cudaFuncSetAttribute(gemm_mma_kernel, cudaFuncAttributeMaxDynamicSharedMemorySize, SMEM_TOTAL);

    split_transpose_kernel<<<dim3(KDIM / 32, NDFv / 32), 256>>>(w_emb);
    gemm_mma_kernel<<<128, 256, SMEM_TOTAL>>>(z_roi);
    reduce_kernel<<<(MROWS * NDFv / 2) / 256, 256>>>(b_emb, mask, zall);
    cluster_kernel<<<MROWS / 8, 128>>>(zall, cent, mask, S, Cx);
}

// round 6
// speedup vs baseline: 2.6364x; 1.0159x over previous
#include <cuda_runtime.h>
#include <cuda_bf16.h>
#include <cstdint>

#define KDIM   65536
#define MROWS  2048
#define NDFv   256
#define NCv    100
#define SPLITS 8
#define KPS    (KDIM / SPLITS)   // 8192
#define KC     64
#define NCHUNK (KPS / KC)        // 128
#define OFF_AHI 0
#define OFF_ALO 16384
#define OFF_BHI 32768
#define OFF_BLO 65536
#define STAGE   98304
#define SMEM_TOTAL (2 * STAGE)   // 192 KB

// device-global scratch (no cudaMalloc allowed)
__device__ __align__(16) unsigned short g_Bt_hi[(size_t)NDFv * KDIM]; // [n][k] bf16
__device__ __align__(16) unsigned short g_Bt_lo[(size_t)NDFv * KDIM];
__device__ float g_partial[(size_t)SPLITS * MROWS * NDFv];            // [split][row][col]

// ---------------- helpers (sm_80-class PTX only: valid on compute_103) ------
__device__ __forceinline__ uint32_t smem_u32(const void* p) {
    uint32_t a;
    asm("{ .reg .u64 t; cvta.to.shared.u64 t, %1; cvt.u32.u64 %0, t; }" : "=r"(a) : "l"(p));
    return a;
}
__device__ __forceinline__ uint32_t pack2(float lo, float hi) { // low half = bf16(lo)
    uint32_t r;
    asm("cvt.rn.bf16x2.f32 %0, %1, %2;" : "=r"(r) : "f"(hi), "f"(lo));
    return r;
}
#define STS64V(a, r0, r1) \
    asm volatile("st.shared.v2.b32 [%0], {%1,%2};" :: "r"(a), "r"(r0), "r"(r1) : "memory")
#define CP_ASYNC16(dst, src) \
    asm volatile("cp.async.cg.shared.global [%0], [%1], 16;" :: "r"(dst), "l"(src) : "memory")
#define CP_COMMIT() asm volatile("cp.async.commit_group;" ::: "memory")
#define CP_WAIT0()  asm volatile("cp.async.wait_group 0;" ::: "memory")

__device__ __forceinline__ void ldsm4(uint32_t r[4], uint32_t a) {
    asm volatile("ldmatrix.sync.aligned.m8n8.x4.shared.b16 {%0,%1,%2,%3}, [%4];"
                 : "=r"(r[0]), "=r"(r[1]), "=r"(r[2]), "=r"(r[3]) : "r"(a));
}
__device__ __forceinline__ void mma16816(float d[4], const uint32_t a[4],
                                         uint32_t b0, uint32_t b1) {
    asm volatile("mma.sync.aligned.m16n8k16.row.col.f32.bf16.bf16.f32 "
                 "{%0,%1,%2,%3},{%4,%5,%6,%7},{%8,%9},{%0,%1,%2,%3};"
                 : "+f"(d[0]), "+f"(d[1]), "+f"(d[2]), "+f"(d[3])
                 : "r"(a[0]), "r"(a[1]), "r"(a[2]), "r"(a[3]), "r"(b0), "r"(b1));
}

// ---------------- prepass: w_emb [K,256] fp32 -> g_Bt_{hi,lo} [256][K] bf16 --
__global__ __launch_bounds__(256) void split_transpose_kernel(const float* __restrict__ W) {
    __shared__ float tile[32][33];
    const int k0 = blockIdx.x * 32, n0 = blockIdx.y * 32;
    const int tx = threadIdx.x & 31, ty = threadIdx.x >> 5;
    #pragma unroll
    for (int i = 0; i < 4; i++)
        tile[ty * 4 + i][tx] = W[(size_t)(k0 + ty * 4 + i) * NDFv + n0 + tx];
    __syncthreads();
    #pragma unroll
    for (int i = 0; i < 4; i++) {
        const int n = ty * 4 + i;
        const float v = tile[tx][n];
        __nv_bfloat16 h = __float2bfloat16(v);
        __nv_bfloat16 l = __float2bfloat16(v - __bfloat162float(h));
        const size_t idx = (size_t)(n0 + n) * KDIM + k0 + tx;
        g_Bt_hi[idx] = *(unsigned short*)&h;
        g_Bt_lo[idx] = *(unsigned short*)&l;
    }
}

// ---------------- GEMM: mma.sync bf16 3-way split, CTA tile 128x256 ---------
__global__ __launch_bounds__(256, 1) void gemm_mma_kernel(const float* __restrict__ A) {
    extern __shared__ char smem_dyn[];
    const uint32_t sbase = smem_u32(smem_dyn);
    const int tid = threadIdx.x;
    const int wid = tid >> 5, lane = tid & 31;
    const int mtile = blockIdx.x & 15;
    const int split = blockIdx.x >> 4;
    const int wm = wid & 1, wn = wid >> 1;   // warp tile: m64 x n64

    // A loader: 2 threads per row (128 rows), each 32 k = 8 float4
    const int arow = tid >> 1, ahalf = tid & 1;
    const uint32_t xa = (uint32_t)((arow & 7) << 4);
    const float* Ag = A + (size_t)(mtile * 128 + arow) * KDIM + (size_t)split * KPS + ahalf * 32;
    // B loader: 1 thread per n-row (256 rows), 64 k = 8 x 16B per array
    const uint32_t xb = (uint32_t)((tid & 7) << 4);
    const unsigned short* Bhg = g_Bt_hi + (size_t)tid * KDIM + (size_t)split * KPS;
    const unsigned short* Blg = g_Bt_lo + (size_t)tid * KDIM + (size_t)split * KPS;
    const uint32_t brow_off = (uint32_t)(tid * 128);

    // ldmatrix lane mapping
    const int a_r = (lane & 7) + ((lane >> 3) & 1) * 8;
    const uint32_t a_c16 = (uint32_t)(((lane >> 4) & 1) * 16);
    const uint32_t xf = (uint32_t)((a_r & 7) << 4);
    uint32_t colx[4];
    #pragma unroll
    for (int ks = 0; ks < 4; ks++) colx[ks] = (((uint32_t)ks << 5) | a_c16) ^ xf;

    float acc[4][8][4] = {};
    float4 a_ld[8];

    // prologue: chunk 0
    #pragma unroll
    for (int i = 0; i < 8; i++) a_ld[i] = *(const float4*)(Ag + i * 4);
    #pragma unroll
    for (int j = 0; j < 4; j++) {
        const uint32_t off = brow_off + ((((uint32_t)j) << 4) ^ xb);
        CP_ASYNC16(sbase + OFF_BHI + off, Bhg + j * 8);
        CP_ASYNC16(sbase + OFF_BLO + off, Blg + j * 8);
        const uint32_t off2 = brow_off + ((((uint32_t)(j + 4)) << 4) ^ xb);
        CP_ASYNC16(sbase + OFF_BHI + off2, Bhg + (j + 4) * 8);
        CP_ASYNC16(sbase + OFF_BLO + off2, Blg + (j + 4) * 8);
    }
    CP_COMMIT();

    for (int it = 0; it < NCHUNK; it++) {
        const uint32_t st = sbase + (uint32_t)((it & 1) * STAGE);

        // A: fp32 regs -> bf16 hi/lo -> swizzled STS
        #pragma unroll
        for (int i = 0; i < 8; i++) {
            const float4 f = a_ld[i];
            const uint32_t h0 = pack2(f.x, f.y);
            const uint32_t h1 = pack2(f.z, f.w);
            const uint32_t l0 = pack2(f.x - __uint_as_float(h0 << 16),
                                      f.y - __uint_as_float(h0 & 0xffff0000u));
            const uint32_t l1 = pack2(f.z - __uint_as_float(h1 << 16),
                                      f.w - __uint_as_float(h1 & 0xffff0000u));
            const uint32_t off = (uint32_t)(arow * 128) +
                                 (((uint32_t)(ahalf * 64 + i * 8)) ^ xa);
            STS64V(st + OFF_AHI + off, h0, h1);
            STS64V(st + OFF_ALO + off, l0, l1);
        }
        CP_WAIT0();            // only this stage's B group is outstanding here
        __syncthreads();

        // prefetch next chunk
        if (it + 1 < NCHUNK) {
            const float* Ap = Ag + (size_t)(it + 1) * KC;
            #pragma unroll
            for (int i = 0; i < 8; i++) a_ld[i] = *(const float4*)(Ap + i * 4);
            const uint32_t st2 = sbase + (uint32_t)(((it + 1) & 1) * STAGE);
            const unsigned short* Bhp = Bhg + (size_t)(it + 1) * KC;
            const unsigned short* Blp = Blg + (size_t)(it + 1) * KC;
            #pragma unroll
            for (int j = 0; j < 8; j++) {
                const uint32_t off = brow_off + ((((uint32_t)j) << 4) ^ xb);
                CP_ASYNC16(st2 + OFF_BHI + off, Bhp + j * 8);
                CP_ASYNC16(st2 + OFF_BLO + off, Blp + j * 8);
            }
            CP_COMMIT();
        }

        // tensor-core mainloop on stage st
        #pragma unroll
        for (int ks = 0; ks < 4; ks++) {
            uint32_t ah[4][4], al[4][4];
            #pragma unroll
            for (int mf = 0; mf < 4; mf++) {
                const uint32_t ro = (uint32_t)((wm * 64 + mf * 16 + a_r) * 128) + colx[ks];
                ldsm4(ah[mf], st + OFF_AHI + ro);
                ldsm4(al[mf], st + OFF_ALO + ro);
            }
            uint32_t bh[4][4];
            #pragma unroll
            for (int g = 0; g < 4; g++) {
                const uint32_t ro = (uint32_t)((wn * 64 + g * 16 + a_r) * 128) + colx[ks];
                ldsm4(bh[g], st + OFF_BHI + ro);
            }
            #pragma unroll
            for (int mf = 0; mf < 4; mf++)
                #pragma unroll
                for (int g = 0; g < 4; g++) {
                    mma16816(acc[mf][g * 2 + 0], ah[mf], bh[g][0], bh[g][2]); // Ahi*Bhi
                    mma16816(acc[mf][g * 2 + 1], ah[mf], bh[g][1], bh[g][3]);
                    mma16816(acc[mf][g * 2 + 0], al[mf], bh[g][0], bh[g][2]); // Alo*Bhi
                    mma16816(acc[mf][g * 2 + 1], al[mf], bh[g][1], bh[g][3]);
                }
            uint32_t bl[4][4];
            #pragma unroll
            for (int g = 0; g < 4; g++) {
                const uint32_t ro = (uint32_t)((wn * 64 + g * 16 + a_r) * 128) + colx[ks];
                ldsm4(bl[g], st + OFF_BLO + ro);
            }
            #pragma unroll
            for (int mf = 0; mf < 4; mf++)
                #pragma unroll
                for (int g = 0; g < 4; g++) {
                    mma16816(acc[mf][g * 2 + 0], ah[mf], bl[g][0], bl[g][2]); // Ahi*Blo
                    mma16816(acc[mf][g * 2 + 1], ah[mf], bl[g][1], bl[g][3]);
                }
        }
    }

    // epilogue: split partials [split][row][col]
    float* pbase = g_partial + (size_t)split * MROWS * NDFv;
    #pragma unroll
    for (int mf = 0; mf < 4; mf++)
        #pragma unroll
        for (int nf = 0; nf < 8; nf++) {
            const int row = mtile * 128 + wm * 64 + mf * 16 + (lane >> 2);
            const int col = wn * 64 + nf * 8 + (lane & 3) * 2;
            float* p = pbase + (size_t)row * NDFv + col;
            *(float2*)p = make_float2(acc[mf][nf][0], acc[mf][nf][1]);
            *(float2*)(p + 8 * NDFv) = make_float2(acc[mf][nf][2], acc[mf][nf][3]);
        }
}

// ---------------- split-K reduce: zall = (sum partials + bias) * mask -------
__global__ __launch_bounds__(256) void reduce_kernel(const float* __restrict__ bias,
                                                     const int* __restrict__ mask,
                                                     float* __restrict__ zall) {
    const int i = blockIdx.x * 256 + threadIdx.x;   // float2 units
    const int row = i >> 7;
    const int col = (i & 127) * 2;
    float2 s = make_float2(0.f, 0.f);
    #pragma unroll
    for (int sp = 0; sp < SPLITS; sp++) {
        const float2 v = *(const float2*)&g_partial[(size_t)sp * MROWS * NDFv +
                                                    (size_t)row * NDFv + col];
        s.x += v.x; s.y += v.y;
    }
    const float m = mask[row] ? 1.0f : 0.0f;
    s.x = (s.x + bias[col]) * m;
    s.y = (s.y + bias[col + 1]) * m;
    *(float2*)&zall[(size_t)row * NDFv + col] = s;
}

// ---------------- student-t + normalize + argmax (2 rows / block, ILP x2) ---
__global__ __launch_bounds__(128) void cluster_kernel(const float* __restrict__ Z,
                                                      const float* __restrict__ cent,
                                                      const int* __restrict__ mask,
                                                      float* __restrict__ S,
                                                      float* __restrict__ Cidx) {
    const int tid = threadIdx.x;
    const int row0 = blockIdx.x * 2;
    __shared__ __align__(16) float zs[2][256];
    __shared__ float stmp[2][128];
    __shared__ float red_s[2];
    __shared__ int   red_i[2];

    #pragma unroll
    for (int i = 0; i < 4; i++) {
        const int idx = i * 128 + tid;
        zs[idx >> 8][idx & 255] = Z[(size_t)row0 * 256 + idx];
    }
    __syncthreads();

    float v0 = 0.0f, v1 = 0.0f;
    if (tid < NCv) {
        const float4* c4 = (const float4*)(cent + (size_t)tid * NDFv);
        const float4* z0 = (const float4*)zs[0];
        const float4* z1 = (const float4*)zs[1];
        float d0 = 0.0f, d1 = 0.0f;
        #pragma unroll 8
        for (int j = 0; j < NDFv / 4; j++) {
            const float4 cv = c4[j];
            const float4 a = z0[j];
            const float4 b = z1[j];
            float dx = a.x - cv.x, dy = a.y - cv.y, dz = a.z - cv.z, dw = a.w - cv.w;
            d0 += dx * dx + dy * dy + dz * dz + dw * dw;
            dx = b.x - cv.x; dy = b.y - cv.y; dz = b.z - cv.z; dw = b.w - cv.w;
            d1 += dx * dx + dy * dy + dz * dz + dw * dw;
        }
        v0 = 1.0f / (1.0f + sqrtf(fmaxf(d0, 0.0f)));
        v1 = 1.0f / (1.0f + sqrtf(fmaxf(d1, 0.0f)));
    }
    stmp[0][tid] = v0;
    stmp[1][tid] = v1;
    __syncthreads();

    if (tid < 64) {  // warps 0,1 reduce rows 0,1
        const int r = tid >> 5, l = tid & 31;
        float sum = 0.0f, best = -1.0f;
        int bidx = 0;
        for (int k = l; k < NCv; k += 32) {
            const float v = stmp[r][k];
            sum += v;
            if (v > best) { best = v; bidx = k; }
        }
        #pragma unroll
        for (int off = 16; off > 0; off >>= 1) {
            sum += __shfl_down_sync(0xffffffffu, sum, off);
            const float ob = __shfl_down_sync(0xffffffffu, best, off);
            const int   oi = __shfl_down_sync(0xffffffffu, bidx, off);
            if (ob > best || (ob == best && oi < bidx)) { best = ob; bidx = oi; }
        }
        if (l == 0) { red_s[r] = sum; red_i[r] = bidx; }
    }
    __syncthreads();

    #pragma unroll
    for (int r = 0; r < 2; r++) {
        const int row = row0 + r;
        const bool m = mask[row] != 0;
        const float inv = m ? (1.0f / red_s[r]) : 0.0f;
        if (tid < NCv) S[(size_t)row * NCv + tid] = (r ? v1 : v0) * inv;
        if (tid == 0)  Cidx[row] = m ? (float)red_i[r] : 0.0f;
    }
}

// ---------------------------------------------------------------------------
extern "C" void kernel_launch(void* const* d_in, const int* in_sizes, int n_in,
                              void* d_out, int out_size) {
    (void)in_sizes; (void)n_in; (void)out_size;
    const float* z_roi = (const float*)d_in[0];
    const int*   mask  = (const int*)d_in[1];
    const float* w_emb = (const float*)d_in[2];
    const float* b_emb = (const float*)d_in[3];
    const float* cent  = (const float*)d_in[4];

    float* out  = (float*)d_out;
    float* zall = out;
    float* S    = out + (size_t)MROWS * NDFv;
    float* Cx   = S + (size_t)MROWS * NCv;

    cudaFuncSetAttribute(gemm_mma_kernel, cudaFuncAttributeMaxDynamicSharedMemorySize, SMEM_TOTAL);

    split_transpose_kernel<<<dim3(KDIM / 32, NDFv / 32), 256>>>(w_emb);
    gemm_mma_kernel<<<128, 256, SMEM_TOTAL>>>(z_roi);
    reduce_kernel<<<(MROWS * NDFv / 2) / 256, 256>>>(b_emb, mask, zall);
    cluster_kernel<<<MROWS / 2, 128>>>(zall, cent, mask, S, Cx);
}

// round 7
// speedup vs baseline: 2.6415x; 1.0019x over previous
#include <cuda_runtime.h>
#include <cuda_bf16.h>
#include <cstdint>

#define KDIM   65536
#define MROWS  2048
#define NDFv   256
#define NCv    100
#define SPLITS 8
#define KPS    (KDIM / SPLITS)   // 8192
#define KC     64
#define NCHUNK (KPS / KC)        // 128
#define OFF_AHI 0
#define OFF_ALO 16384
#define OFF_BHI 32768
#define OFF_BLO 65536
#define STAGE   98304
#define SMEM_TOTAL (2 * STAGE)   // 192 KB

// device-global scratch (no cudaMalloc allowed)
__device__ __align__(16) unsigned short g_Bt_hi[(size_t)NDFv * KDIM]; // [n][k] bf16
__device__ __align__(16) unsigned short g_Bt_lo[(size_t)NDFv * KDIM];
__device__ float g_partial[(size_t)SPLITS * MROWS * NDFv];            // [split][row][col]

// ---------------- helpers (sm_80-class PTX only: valid on compute_103) ------
__device__ __forceinline__ uint32_t smem_u32(const void* p) {
    uint32_t a;
    asm("{ .reg .u64 t; cvta.to.shared.u64 t, %1; cvt.u32.u64 %0, t; }" : "=r"(a) : "l"(p));
    return a;
}
__device__ __forceinline__ uint32_t pack2(float lo, float hi) { // low half = bf16(lo)
    uint32_t r;
    asm("cvt.rn.bf16x2.f32 %0, %1, %2;" : "=r"(r) : "f"(hi), "f"(lo));
    return r;
}
#define STS64V(a, r0, r1) \
    asm volatile("st.shared.v2.b32 [%0], {%1,%2};" :: "r"(a), "r"(r0), "r"(r1) : "memory")
#define CP_ASYNC16(dst, src) \
    asm volatile("cp.async.cg.shared.global [%0], [%1], 16;" :: "r"(dst), "l"(src) : "memory")
#define CP_COMMIT() asm volatile("cp.async.commit_group;" ::: "memory")
#define CP_WAIT0()  asm volatile("cp.async.wait_group 0;" ::: "memory")

__device__ __forceinline__ void ldsm4(uint32_t r[4], uint32_t a) {
    asm volatile("ldmatrix.sync.aligned.m8n8.x4.shared.b16 {%0,%1,%2,%3}, [%4];"
                 : "=r"(r[0]), "=r"(r[1]), "=r"(r[2]), "=r"(r[3]) : "r"(a));
}
__device__ __forceinline__ void mma16816(float d[4], const uint32_t a[4],
                                         uint32_t b0, uint32_t b1) {
    asm volatile("mma.sync.aligned.m16n8k16.row.col.f32.bf16.bf16.f32 "
                 "{%0,%1,%2,%3},{%4,%5,%6,%7},{%8,%9},{%0,%1,%2,%3};"
                 : "+f"(d[0]), "+f"(d[1]), "+f"(d[2]), "+f"(d[3])
                 : "r"(a[0]), "r"(a[1]), "r"(a[2]), "r"(a[3]), "r"(b0), "r"(b1));
}

// ---------------- prepass: w_emb [K,256] fp32 -> g_Bt_{hi,lo} [256][K] bf16 --
__global__ __launch_bounds__(256) void split_transpose_kernel(const float* __restrict__ W) {
    __shared__ float tile[32][33];
    const int k0 = blockIdx.x * 32, n0 = blockIdx.y * 32;
    const int tx = threadIdx.x & 31, ty = threadIdx.x >> 5;
    #pragma unroll
    for (int i = 0; i < 4; i++)
        tile[ty * 4 + i][tx] = W[(size_t)(k0 + ty * 4 + i) * NDFv + n0 + tx];
    __syncthreads();
    #pragma unroll
    for (int i = 0; i < 4; i++) {
        const int n = ty * 4 + i;
        const float v = tile[tx][n];
        __nv_bfloat16 h = __float2bfloat16(v);
        __nv_bfloat16 l = __float2bfloat16(v - __bfloat162float(h));
        const size_t idx = (size_t)(n0 + n) * KDIM + k0 + tx;
        g_Bt_hi[idx] = *(unsigned short*)&h;
        g_Bt_lo[idx] = *(unsigned short*)&l;
    }
}

// ---------------- GEMM: mma.sync bf16 3-way split, CTA tile 128x256 ---------
// Inner loop reorganized into three independent MMA passes per k-step to
// eliminate back-to-back RAW dependencies on accumulators.
__global__ __launch_bounds__(256, 1) void gemm_mma_kernel(const float* __restrict__ A) {
    extern __shared__ char smem_dyn[];
    const uint32_t sbase = smem_u32(smem_dyn);
    const int tid = threadIdx.x;
    const int wid = tid >> 5, lane = tid & 31;
    const int mtile = blockIdx.x & 15;
    const int split = blockIdx.x >> 4;
    const int wm = wid & 1, wn = wid >> 1;   // warp tile: m64 x n64

    // A loader: 2 threads per row (128 rows), each 32 k = 8 float4
    const int arow = tid >> 1, ahalf = tid & 1;
    const uint32_t xa = (uint32_t)((arow & 7) << 4);
    const float* Ag = A + (size_t)(mtile * 128 + arow) * KDIM + (size_t)split * KPS + ahalf * 32;
    // B loader: 1 thread per n-row (256 rows), 64 k = 8 x 16B per array
    const uint32_t xb = (uint32_t)((tid & 7) << 4);
    const unsigned short* Bhg = g_Bt_hi + (size_t)tid * KDIM + (size_t)split * KPS;
    const unsigned short* Blg = g_Bt_lo + (size_t)tid * KDIM + (size_t)split * KPS;
    const uint32_t brow_off = (uint32_t)(tid * 128);

    // ldmatrix lane mapping
    const int a_r = (lane & 7) + ((lane >> 3) & 1) * 8;
    const uint32_t a_c16 = (uint32_t)(((lane >> 4) & 1) * 16);
    const uint32_t xf = (uint32_t)((a_r & 7) << 4);
    uint32_t colx[4];
    #pragma unroll
    for (int ks = 0; ks < 4; ks++) colx[ks] = (((uint32_t)ks << 5) | a_c16) ^ xf;

    float acc[4][8][4] = {};
    float4 a_ld[8];

    // prologue: chunk 0
    #pragma unroll
    for (int i = 0; i < 8; i++) a_ld[i] = *(const float4*)(Ag + i * 4);
    #pragma unroll
    for (int j = 0; j < 8; j++) {
        const uint32_t off = brow_off + ((((uint32_t)j) << 4) ^ xb);
        CP_ASYNC16(sbase + OFF_BHI + off, Bhg + j * 8);
        CP_ASYNC16(sbase + OFF_BLO + off, Blg + j * 8);
    }
    CP_COMMIT();

    for (int it = 0; it < NCHUNK; it++) {
        const uint32_t st = sbase + (uint32_t)((it & 1) * STAGE);

        // A: fp32 regs -> bf16 hi/lo -> swizzled STS
        #pragma unroll
        for (int i = 0; i < 8; i++) {
            const float4 f = a_ld[i];
            const uint32_t h0 = pack2(f.x, f.y);
            const uint32_t h1 = pack2(f.z, f.w);
            const uint32_t l0 = pack2(f.x - __uint_as_float(h0 << 16),
                                      f.y - __uint_as_float(h0 & 0xffff0000u));
            const uint32_t l1 = pack2(f.z - __uint_as_float(h1 << 16),
                                      f.w - __uint_as_float(h1 & 0xffff0000u));
            const uint32_t off = (uint32_t)(arow * 128) +
                                 (((uint32_t)(ahalf * 64 + i * 8)) ^ xa);
            STS64V(st + OFF_AHI + off, h0, h1);
            STS64V(st + OFF_ALO + off, l0, l1);
        }
        CP_WAIT0();
        __syncthreads();

        // prefetch next chunk (A regs via LDG, B via cp.async into other stage)
        if (it + 1 < NCHUNK) {
            const float* Ap = Ag + (size_t)(it + 1) * KC;
            #pragma unroll
            for (int i = 0; i < 8; i++) a_ld[i] = *(const float4*)(Ap + i * 4);
            const uint32_t st2 = sbase + (uint32_t)(((it + 1) & 1) * STAGE);
            const unsigned short* Bhp = Bhg + (size_t)(it + 1) * KC;
            const unsigned short* Blp = Blg + (size_t)(it + 1) * KC;
            #pragma unroll
            for (int j = 0; j < 8; j++) {
                const uint32_t off = brow_off + ((((uint32_t)j) << 4) ^ xb);
                CP_ASYNC16(st2 + OFF_BHI + off, Bhp + j * 8);
                CP_ASYNC16(st2 + OFF_BLO + off, Blp + j * 8);
            }
            CP_COMMIT();
        }

        // tensor-core mainloop on stage st: 3 stall-free passes per k-step
        #pragma unroll
        for (int ks = 0; ks < 4; ks++) {
            uint32_t ah[4][4], al[4][4], bh[4][4], bl[4][4];
            #pragma unroll
            for (int mf = 0; mf < 4; mf++) {
                const uint32_t ro = (uint32_t)((wm * 64 + mf * 16 + a_r) * 128) + colx[ks];
                ldsm4(ah[mf], st + OFF_AHI + ro);
            }
            #pragma unroll
            for (int g = 0; g < 4; g++) {
                const uint32_t ro = (uint32_t)((wn * 64 + g * 16 + a_r) * 128) + colx[ks];
                ldsm4(bh[g], st + OFF_BHI + ro);
            }
            // pass 1: Ahi * Bhi — 32 independent MMAs
            #pragma unroll
            for (int mf = 0; mf < 4; mf++)
                #pragma unroll
                for (int g = 0; g < 4; g++) {
                    mma16816(acc[mf][g * 2 + 0], ah[mf], bh[g][0], bh[g][2]);
                    mma16816(acc[mf][g * 2 + 1], ah[mf], bh[g][1], bh[g][3]);
                }
            #pragma unroll
            for (int mf = 0; mf < 4; mf++) {
                const uint32_t ro = (uint32_t)((wm * 64 + mf * 16 + a_r) * 128) + colx[ks];
                ldsm4(al[mf], st + OFF_ALO + ro);
            }
            // pass 2: Alo * Bhi — 32 independent MMAs
            #pragma unroll
            for (int mf = 0; mf < 4; mf++)
                #pragma unroll
                for (int g = 0; g < 4; g++) {
                    mma16816(acc[mf][g * 2 + 0], al[mf], bh[g][0], bh[g][2]);
                    mma16816(acc[mf][g * 2 + 1], al[mf], bh[g][1], bh[g][3]);
                }
            #pragma unroll
            for (int g = 0; g < 4; g++) {
                const uint32_t ro = (uint32_t)((wn * 64 + g * 16 + a_r) * 128) + colx[ks];
                ldsm4(bl[g], st + OFF_BLO + ro);
            }
            // pass 3: Ahi * Blo — 32 independent MMAs
            #pragma unroll
            for (int mf = 0; mf < 4; mf++)
                #pragma unroll
                for (int g = 0; g < 4; g++) {
                    mma16816(acc[mf][g * 2 + 0], ah[mf], bl[g][0], bl[g][2]);
                    mma16816(acc[mf][g * 2 + 1], ah[mf], bl[g][1], bl[g][3]);
                }
        }
    }

    // epilogue: split partials [split][row][col]
    float* pbase = g_partial + (size_t)split * MROWS * NDFv;
    #pragma unroll
    for (int mf = 0; mf < 4; mf++)
        #pragma unroll
        for (int nf = 0; nf < 8; nf++) {
            const int row = mtile * 128 + wm * 64 + mf * 16 + (lane >> 2);
            const int col = wn * 64 + nf * 8 + (lane & 3) * 2;
            float* p = pbase + (size_t)row * NDFv + col;
            *(float2*)p = make_float2(acc[mf][nf][0], acc[mf][nf][1]);
            *(float2*)(p + 8 * NDFv) = make_float2(acc[mf][nf][2], acc[mf][nf][3]);
        }
}

// ---------------- split-K reduce: zall = (sum partials + bias) * mask -------
__global__ __launch_bounds__(256) void reduce_kernel(const float* __restrict__ bias,
                                                     const int* __restrict__ mask,
                                                     float* __restrict__ zall) {
    const int i = blockIdx.x * 256 + threadIdx.x;   // float2 units
    const int row = i >> 7;
    const int col = (i & 127) * 2;
    float2 s = make_float2(0.f, 0.f);
    #pragma unroll
    for (int sp = 0; sp < SPLITS; sp++) {
        const float2 v = *(const float2*)&g_partial[(size_t)sp * MROWS * NDFv +
                                                    (size_t)row * NDFv + col];
        s.x += v.x; s.y += v.y;
    }
    const float m = mask[row] ? 1.0f : 0.0f;
    s.x = (s.x + bias[col]) * m;
    s.y = (s.y + bias[col + 1]) * m;
    *(float2*)&zall[(size_t)row * NDFv + col] = s;
}

// ---------------- student-t + normalize + argmax (2 rows / block, ILP x2) ---
__global__ __launch_bounds__(128) void cluster_kernel(const float* __restrict__ Z,
                                                      const float* __restrict__ cent,
                                                      const int* __restrict__ mask,
                                                      float* __restrict__ S,
                                                      float* __restrict__ Cidx) {
    const int tid = threadIdx.x;
    const int row0 = blockIdx.x * 2;
    __shared__ __align__(16) float zs[2][256];
    __shared__ float stmp[2][128];
    __shared__ float red_s[2];
    __shared__ int   red_i[2];

    #pragma unroll
    for (int i = 0; i < 4; i++) {
        const int idx = i * 128 + tid;
        zs[idx >> 8][idx & 255] = Z[(size_t)row0 * 256 + idx];
    }
    __syncthreads();

    float v0 = 0.0f, v1 = 0.0f;
    if (tid < NCv) {
        const float4* c4 = (const float4*)(cent + (size_t)tid * NDFv);
        const float4* z0 = (const float4*)zs[0];
        const float4* z1 = (const float4*)zs[1];
        float d0 = 0.0f, d1 = 0.0f;
        #pragma unroll 8
        for (int j = 0; j < NDFv / 4; j++) {
            const float4 cv = c4[j];
            const float4 a = z0[j];
            const float4 b = z1[j];
            float dx = a.x - cv.x, dy = a.y - cv.y, dz = a.z - cv.z, dw = a.w - cv.w;
            d0 += dx * dx + dy * dy + dz * dz + dw * dw;
            dx = b.x - cv.x; dy = b.y - cv.y; dz = b.z - cv.z; dw = b.w - cv.w;
            d1 += dx * dx + dy * dy + dz * dz + dw * dw;
        }
        v0 = 1.0f / (1.0f + sqrtf(fmaxf(d0, 0.0f)));
        v1 = 1.0f / (1.0f + sqrtf(fmaxf(d1, 0.0f)));
    }
    stmp[0][tid] = v0;
    stmp[1][tid] = v1;
    __syncthreads();

    if (tid < 64) {  // warps 0,1 reduce rows 0,1
        const int r = tid >> 5, l = tid & 31;
        float sum = 0.0f, best = -1.0f;
        int bidx = 0;
        for (int k = l; k < NCv; k += 32) {
            const float v = stmp[r][k];
            sum += v;
            if (v > best) { best = v; bidx = k; }
        }
        #pragma unroll
        for (int off = 16; off > 0; off >>= 1) {
            sum += __shfl_down_sync(0xffffffffu, sum, off);
            const float ob = __shfl_down_sync(0xffffffffu, best, off);
            const int   oi = __shfl_down_sync(0xffffffffu, bidx, off);
            if (ob > best || (ob == best && oi < bidx)) { best = ob; bidx = oi; }
        }
        if (l == 0) { red_s[r] = sum; red_i[r] = bidx; }
    }
    __syncthreads();

    #pragma unroll
    for (int r = 0; r < 2; r++) {
        const int row = row0 + r;
        const bool m = mask[row] != 0;
        const float inv = m ? (1.0f / red_s[r]) : 0.0f;
        if (tid < NCv) S[(size_t)row * NCv + tid] = (r ? v1 : v0) * inv;
        if (tid == 0)  Cidx[row] = m ? (float)red_i[r] : 0.0f;
    }
}

// ---------------------------------------------------------------------------
extern "C" void kernel_launch(void* const* d_in, const int* in_sizes, int n_in,
                              void* d_out, int out_size) {
    (void)in_sizes; (void)n_in; (void)out_size;
    const float* z_roi = (const float*)d_in[0];
    const int*   mask  = (const int*)d_in[1];
    const float* w_emb = (const float*)d_in[2];
    const float* b_emb = (const float*)d_in[3];
    const float* cent  = (const float*)d_in[4];

    float* out  = (float*)d_out;
    float* zall = out;
    float* S    = out + (size_t)MROWS * NDFv;
    float* Cx   = S + (size_t)MROWS * NCv;

    cudaFuncSetAttribute(gemm_mma_kernel, cudaFuncAttributeMaxDynamicSharedMemorySize, SMEM_TOTAL);

    split_transpose_kernel<<<dim3(KDIM / 32, NDFv / 32), 256>>>(w_emb);
    gemm_mma_kernel<<<128, 256, SMEM_TOTAL>>>(z_roi);
    reduce_kernel<<<(MROWS * NDFv / 2) / 256, 256>>>(b_emb, mask, zall);
    cluster_kernel<<<MROWS / 2, 128>>>(zall, cent, mask, S, Cx);
}